// round 1
// baseline (speedup 1.0000x reference)
#include <cuda_runtime.h>
#include <math.h>
#include <stdint.h>

// Problem constants (fixed by setup_inputs)
#define B_    2
#define L_    1000
#define NQ_   2000
#define EMB_  256
#define G_    4
#define NP_   32
#define P_    128     // G_*NP_
#define CH_   64      // EMB_/G_
#define XDIM_ 8192    // P_*CH_

// Level geometry: H=W = 256,128,64,32 ; strides 4,8,16,32
#define HW0_ 65536
#define HW1_ 16384
#define HW2_ 4096
#define HW3_ 1024

// ---------------- scratch (device globals; no allocations) ----------------
__device__ float g_vt0[(size_t)B_ * HW0_ * EMB_];   // 134 MB channel-last level 0
__device__ float g_vt1[(size_t)B_ * HW1_ * EMB_];   // 33.5 MB
__device__ float g_vt2[(size_t)B_ * HW2_ * EMB_];   // 8.4 MB
__device__ float g_vt3[(size_t)B_ * HW3_ * EMB_];   // 2.1 MB
__device__ float g_OFF[(size_t)NQ_ * 384];
__device__ float g_HCA[(size_t)NQ_ * 64];
__device__ float g_HSA[(size_t)NQ_ * 64];
__device__ float g_CA [(size_t)NQ_ * EMB_];
__device__ float g_SA [(size_t)NQ_ * P_];
__device__ float g_PT [(size_t)NQ_ * P_ * 8];       // sx,sy,w0..w3,sa,pad
__device__ float g_X  [(size_t)NQ_ * XDIM_];        // 65.5 MB
#define SK_ 8
__device__ float g_PART[(size_t)SK_ * NQ_ * EMB_];  // split-K partials

// ---------------- NCHW -> NHWC transpose (per level) ----------------
__global__ void transpose_cl(const float* __restrict__ in, float* __restrict__ out, int HW)
{
    __shared__ __align__(16) float tile[256][33];
    const int b    = blockIdx.y;
    const int pix0 = blockIdx.x * 32;
    const int tid  = threadIdx.x;
    const int lane = tid & 31, cg = tid >> 5;

    const float* inb = in + (size_t)b * 256 * HW;
#pragma unroll
    for (int c = cg; c < 256; c += 8)
        tile[c][lane] = inb[(size_t)c * HW + pix0 + lane];
    __syncthreads();

    float* outb = out + ((size_t)b * HW + pix0) * 256;
#pragma unroll 8
    for (int pp = 0; pp < 32; ++pp)
        outb[(size_t)pp * 256 + tid] = tile[tid][pp];
}

// ---------------- generic small GEMM: C = act(A(MxK) @ W(KxN) [+ bias]) ----------------
// BM=64 BN=64 BK=16, 256 threads, 4x4 microtile. N must be a multiple of 64, K of 16.
// mode: 0 = plain (+bias if non-null), 1 = relu, 2 = sigmoid
__global__ void gemm_small(const float* __restrict__ A, const float* __restrict__ Wm,
                           const float* __restrict__ bias, float* __restrict__ C,
                           int M, int N, int K, int mode)
{
    __shared__ __align__(16) float As[16][68];
    __shared__ __align__(16) float Bs[16][64];
    const int tid = threadIdx.x;
    const int m0 = blockIdx.x * 64, n0 = blockIdx.y * 64;
    const int tx = tid & 15, ty = tid >> 4;

    float acc[4][4] = {};

    const int lm = tid >> 2;          // 0..63  (A row within tile)
    const int lk = (tid & 3) * 4;     // 0,4,8,12
    const int bk = tid >> 4;          // 0..15  (B row)
    const int bn = (tid & 15) * 4;

    for (int k0 = 0; k0 < K; k0 += 16) {
        float4 av = make_float4(0.f, 0.f, 0.f, 0.f);
        if (m0 + lm < M)
            av = *(const float4*)(A + (size_t)(m0 + lm) * K + k0 + lk);
        As[lk + 0][lm] = av.x; As[lk + 1][lm] = av.y;
        As[lk + 2][lm] = av.z; As[lk + 3][lm] = av.w;

        float4 bv = *(const float4*)(Wm + (size_t)(k0 + bk) * N + n0 + bn);
        *(float4*)&Bs[bk][bn] = bv;
        __syncthreads();

#pragma unroll
        for (int kk = 0; kk < 16; ++kk) {
            float a[4], b[4];
            *(float4*)a = *(const float4*)&As[kk][ty * 4];
            *(float4*)b = *(const float4*)&Bs[kk][tx * 4];
#pragma unroll
            for (int i = 0; i < 4; ++i)
#pragma unroll
                for (int j = 0; j < 4; ++j)
                    acc[i][j] += a[i] * b[j];
        }
        __syncthreads();
    }

#pragma unroll
    for (int i = 0; i < 4; ++i) {
        const int row = m0 + ty * 4 + i;
        if (row >= M) continue;
#pragma unroll
        for (int j = 0; j < 4; ++j) {
            const int col = n0 + tx * 4 + j;
            float v = acc[i][j];
            if (bias) v += bias[col];
            if (mode == 1)       v = fmaxf(v, 0.f);
            else if (mode == 2)  v = 1.f / (1.f + expf(-v));
            C[(size_t)row * N + col] = v;
        }
    }
}

// ---------------- split-K GEMM (final 2000x8192x256): partials to g_PART ----------------
// BM=128 BN=128 BK=8, 256 threads, 8x8 microtile, grid.z = SK_ k-slices.
__global__ void gemm_splitk(const float* __restrict__ A, const float* __restrict__ Wm,
                            float* __restrict__ part, int M, int N, int K)
{
    __shared__ __align__(16) float As[8][128];
    __shared__ __align__(16) float Bs[8][128];
    const int tid = threadIdx.x;
    const int m0 = blockIdx.x * 128, n0 = blockIdx.y * 128;
    const int kb = blockIdx.z;
    const int Kc = K / SK_;
    const int kstart = kb * Kc;
    const int tx = tid & 15, ty = tid >> 4;

    float acc[8][8] = {};

    const int am = tid & 127;
    const int ak = (tid >> 7) * 4;   // 0 or 4
    const int bk = tid >> 5;         // 0..7
    const int bn = (tid & 31) * 4;

    const bool arow_ok = (m0 + am) < M;
    const float* Arow = A + (size_t)(m0 + am) * K;

    for (int k0 = kstart; k0 < kstart + Kc; k0 += 8) {
        float4 av = make_float4(0.f, 0.f, 0.f, 0.f);
        if (arow_ok) av = *(const float4*)(Arow + k0 + ak);
        As[ak + 0][am] = av.x; As[ak + 1][am] = av.y;
        As[ak + 2][am] = av.z; As[ak + 3][am] = av.w;

        float4 bv = *(const float4*)(Wm + (size_t)(k0 + bk) * N + n0 + bn);
        *(float4*)&Bs[bk][bn] = bv;
        __syncthreads();

#pragma unroll
        for (int kk = 0; kk < 8; ++kk) {
            float a[8], b[8];
            *(float4*)&a[0] = *(const float4*)&As[kk][ty * 8];
            *(float4*)&a[4] = *(const float4*)&As[kk][ty * 8 + 4];
            *(float4*)&b[0] = *(const float4*)&Bs[kk][tx * 8];
            *(float4*)&b[4] = *(const float4*)&Bs[kk][tx * 8 + 4];
#pragma unroll
            for (int i = 0; i < 8; ++i)
#pragma unroll
                for (int j = 0; j < 8; ++j)
                    acc[i][j] += a[i] * b[j];
        }
        __syncthreads();
    }

    float* pbase = part + (size_t)kb * M * N;
#pragma unroll
    for (int i = 0; i < 8; ++i) {
        const int row = m0 + ty * 8 + i;
        if (row >= M) continue;
        float4 o0 = make_float4(acc[i][0], acc[i][1], acc[i][2], acc[i][3]);
        float4 o1 = make_float4(acc[i][4], acc[i][5], acc[i][6], acc[i][7]);
        float* dst = pbase + (size_t)row * N + n0 + tx * 8;
        *(float4*)dst       = o0;
        *(float4*)(dst + 4) = o1;
    }
}

// ---------------- reduce partials + bias + residual ----------------
__global__ void reduce_out(const float* __restrict__ part, const float* __restrict__ bias,
                           const float* __restrict__ resid, float* __restrict__ out, int total)
{
    const int idx = blockIdx.x * blockDim.x + threadIdx.x;
    if (idx >= total) return;
    float s = 0.f;
#pragma unroll
    for (int kb = 0; kb < SK_; ++kb)
        s += part[(size_t)kb * total + idx];
    out[idx] = s + bias[idx & (EMB_ - 1)] + resid[idx];
}

// ---------------- per-point geometry prep ----------------
__global__ void point_prep(const float* __restrict__ OFF, const float* __restrict__ xyzrt,
                           const float* __restrict__ SA, float* __restrict__ PT)
{
    const int q = blockIdx.x;
    const int p = threadIdx.x;   // 0..127

    const float x  = xyzrt[q * 5 + 0];
    const float y  = xyzrt[q * 5 + 1];
    const float z  = xyzrt[q * 5 + 2];
    const float r  = xyzrt[q * 5 + 3];
    const float th = xyzrt[q * 5 + 4];

    const float ox = OFF[(size_t)q * 384 + p * 3 + 0];
    const float oy = OFF[(size_t)q * 384 + p * 3 + 1];
    const float oz = OFF[(size_t)q * 384 + p * 3 + 2];

    const float rw = exp2f(z - 0.5f * r);   // roi width
    const float rh = exp2f(z + 0.5f * r);   // roi height
    float sth, cth;
    sincosf(th, &sth, &cth);

    const float offx = ox * rw;
    const float offy = oy * rh;
    const float sx = x + cth * offx - sth * offy;
    const float sy = y + sth * offx + cth * offy;
    const float sz = z + oz;

    float w[4];
#pragma unroll
    for (int lvl = 0; lvl < 4; ++lvl) {
        const float d = sz - (float)(2 + lvl);   // log2(stride) = 2,3,4,5
        w[lvl] = 1.f / (1.f + expf(0.5f * d * d));
    }

    float* o = PT + ((size_t)q * P_ + p) * 8;
    float4 o0 = make_float4(sx, sy, w[0], w[1]);
    float4 o1 = make_float4(w[2], w[3], SA[(size_t)q * P_ + p], 0.f);
    *(float4*)o       = o0;
    *(float4*)(o + 4) = o1;
}

// ---------------- bilinear sampler over 4 levels (channel-last) ----------------
__device__ __forceinline__ void samp_lvl(const float* __restrict__ vb, int WW,
                                         float inv, float w, float sx, float sy,
                                         float& a0, float& a1, float& a2, float& a3)
{
    const float ix = sx * inv - 0.5f;
    const float iy = sy * inv - 0.5f;
    const float x0f = floorf(ix), y0f = floorf(iy);
    const float wx1 = ix - x0f, wy1 = iy - y0f;
    const float wx0 = 1.f - wx1, wy0 = 1.f - wy1;
    const int x0 = (int)x0f, y0 = (int)y0f;
    const int x1 = x0 + 1,   y1 = y0 + 1;
    const bool vx0 = (x0 >= 0) & (x0 < WW);
    const bool vx1 = (x1 >= 0) & (x1 < WW);

    if ((y0 >= 0) & (y0 < WW)) {
        const float* row = vb + (size_t)y0 * WW * 256;
        if (vx0) { const float ww = w * wx0 * wy0; const float4 v = *(const float4*)(row + (size_t)x0 * 256);
                   a0 += ww * v.x; a1 += ww * v.y; a2 += ww * v.z; a3 += ww * v.w; }
        if (vx1) { const float ww = w * wx1 * wy0; const float4 v = *(const float4*)(row + (size_t)x1 * 256);
                   a0 += ww * v.x; a1 += ww * v.y; a2 += ww * v.z; a3 += ww * v.w; }
    }
    if ((y1 >= 0) & (y1 < WW)) {
        const float* row = vb + (size_t)y1 * WW * 256;
        if (vx0) { const float ww = w * wx0 * wy1; const float4 v = *(const float4*)(row + (size_t)x0 * 256);
                   a0 += ww * v.x; a1 += ww * v.y; a2 += ww * v.z; a3 += ww * v.w; }
        if (vx1) { const float ww = w * wx1 * wy1; const float4 v = *(const float4*)(row + (size_t)x1 * 256);
                   a0 += ww * v.x; a1 += ww * v.y; a2 += ww * v.z; a3 += ww * v.w; }
    }
}

__global__ void sampler_kernel(const float* __restrict__ PT, const float* __restrict__ CA,
                               float* __restrict__ X)
{
    const int q   = blockIdx.x;
    const int b   = q / L_;
    const int sub = threadIdx.x >> 4;          // 0..15: point within group
    const int c4  = (threadIdx.x & 15) * 4;    // channel quad within head

#pragma unroll 2
    for (int it = 0; it < 8; ++it) {
        const int p = it * 16 + sub;
        const int g = p >> 5;

        const float* pt = PT + ((size_t)q * P_ + p) * 8;
        const float4 pt0 = *(const float4*)pt;        // sx, sy, w0, w1
        const float4 pt1 = *(const float4*)(pt + 4);  // w2, w3, sa, -
        const float4 ca4 = *(const float4*)(CA + (size_t)q * EMB_ + g * CH_ + c4);

        float a0 = 0.f, a1 = 0.f, a2 = 0.f, a3 = 0.f;
        const float sx = pt0.x, sy = pt0.y;
        const int choff = g * CH_ + c4;

        samp_lvl(g_vt0 + (size_t)b * HW0_ * 256 + choff, 256, 0.25f,    pt0.z, sx, sy, a0, a1, a2, a3);
        samp_lvl(g_vt1 + (size_t)b * HW1_ * 256 + choff, 128, 0.125f,   pt0.w, sx, sy, a0, a1, a2, a3);
        samp_lvl(g_vt2 + (size_t)b * HW2_ * 256 + choff,  64, 0.0625f,  pt1.x, sx, sy, a0, a1, a2, a3);
        samp_lvl(g_vt3 + (size_t)b * HW3_ * 256 + choff,  32, 0.03125f, pt1.y, sx, sy, a0, a1, a2, a3);

        const float sam = pt1.z;
        float4 o;
        o.x = a0 * ca4.x * sam;
        o.y = a1 * ca4.y * sam;
        o.z = a2 * ca4.z * sam;
        o.w = a3 * ca4.w * sam;
        *(float4*)(X + (size_t)q * XDIM_ + p * CH_ + c4) = o;
    }
}

// ---------------- launch ----------------
static float* sym_addr(const void* symbol)
{
    void* p = nullptr;
    cudaGetSymbolAddress(&p, symbol);
    return (float*)p;
}

extern "C" void kernel_launch(void* const* d_in, const int* in_sizes, int n_in,
                              void* d_out, int out_size)
{
    const float* v0    = (const float*)d_in[0];
    const float* v1    = (const float*)d_in[1];
    const float* v2    = (const float*)d_in[2];
    const float* v3    = (const float*)d_in[3];
    const float* qc    = (const float*)d_in[4];
    const float* xyzrt = (const float*)d_in[5];
    // d_in[6] strides (int32) -- fixed [4,8,16,32], folded into constants
    const float* W_off = (const float*)d_in[7];
    const float* b_off = (const float*)d_in[8];
    const float* W_ca1 = (const float*)d_in[9];
    const float* W_ca2 = (const float*)d_in[10];
    const float* W_sa1 = (const float*)d_in[11];
    const float* W_sa2 = (const float*)d_in[12];
    const float* W_out = (const float*)d_in[13];
    const float* b_out = (const float*)d_in[14];
    float* out = (float*)d_out;

    float* p_vt0 = sym_addr(g_vt0);
    float* p_vt1 = sym_addr(g_vt1);
    float* p_vt2 = sym_addr(g_vt2);
    float* p_vt3 = sym_addr(g_vt3);
    float* p_OFF = sym_addr(g_OFF);
    float* p_HCA = sym_addr(g_HCA);
    float* p_HSA = sym_addr(g_HSA);
    float* p_CA  = sym_addr(g_CA);
    float* p_SA  = sym_addr(g_SA);
    float* p_PT  = sym_addr(g_PT);
    float* p_X   = sym_addr(g_X);
    float* p_PRT = sym_addr(g_PART);

    // 1) NCHW -> NHWC for all 4 levels
    transpose_cl<<<dim3(HW0_ / 32, B_), 256>>>(v0, p_vt0, HW0_);
    transpose_cl<<<dim3(HW1_ / 32, B_), 256>>>(v1, p_vt1, HW1_);
    transpose_cl<<<dim3(HW2_ / 32, B_), 256>>>(v2, p_vt2, HW2_);
    transpose_cl<<<dim3(HW3_ / 32, B_), 256>>>(v3, p_vt3, HW3_);

    const int gm = (NQ_ + 63) / 64;  // 32

    // 2) projections
    gemm_small<<<dim3(gm, 384 / 64), 256>>>(qc, W_off, b_off, p_OFF, NQ_, 384, EMB_, 0);
    gemm_small<<<dim3(gm, 1),        256>>>(qc, W_ca1, nullptr, p_HCA, NQ_, 64,  EMB_, 1);
    gemm_small<<<dim3(gm, 256 / 64), 256>>>(p_HCA, W_ca2, nullptr, p_CA, NQ_, 256, 64, 2);
    gemm_small<<<dim3(gm, 1),        256>>>(qc, W_sa1, nullptr, p_HSA, NQ_, 64,  EMB_, 1);
    gemm_small<<<dim3(gm, 128 / 64), 256>>>(p_HSA, W_sa2, nullptr, p_SA, NQ_, 128, 64, 2);

    // 3) per-point geometry + level weights
    point_prep<<<NQ_, P_>>>(p_OFF, xyzrt, p_SA, p_PT);

    // 4) bilinear sampling + ca*sa scaling -> X (2000 x 8192)
    sampler_kernel<<<NQ_, 256>>>(p_PT, p_CA, p_X);

    // 5) final GEMM: X @ W_out, split-K partials, then reduce (+bias +residual)
    gemm_splitk<<<dim3((NQ_ + 127) / 128, EMB_ / 128, SK_), 256>>>(p_X, W_out, p_PRT, NQ_, EMB_, XDIM_);
    reduce_out<<<(NQ_ * EMB_ + 255) / 256, 256>>>(p_PRT, b_out, qc, out, NQ_ * EMB_);
}

// round 3
// speedup vs baseline: 1.7563x; 1.7563x over previous
#include <cuda_runtime.h>
#include <cuda_fp16.h>
#include <math.h>
#include <stdint.h>

// Problem constants (fixed by setup_inputs)
#define B_    2
#define L_    1000
#define NQ_   2000
#define MPAD_ 2048    // padded M for GEMM (no guards on A loads)
#define EMB_  256
#define G_    4
#define NP_   32
#define P_    128     // G_*NP_
#define CH_   64      // EMB_/G_
#define XDIM_ 8192    // P_*CH_

// Level geometry: H=W = 256,128,64,32 ; strides 4,8,16,32
#define HW0_ 65536
#define HW1_ 16384
#define HW2_ 4096
#define HW3_ 1024

#define SK_ 4         // split-K factor for final GEMM

// ---------------- scratch (device globals; no allocations) ----------------
__device__ float g_vt0[(size_t)B_ * HW0_ * EMB_];   // 134 MB channel-last level 0
__device__ float g_vt1[(size_t)B_ * HW1_ * EMB_];   // 33.5 MB
__device__ float g_vt2[(size_t)B_ * HW2_ * EMB_];   // 8.4 MB
__device__ float g_vt3[(size_t)B_ * HW3_ * EMB_];   // 2.1 MB
__device__ float g_OFF[(size_t)NQ_ * 384];
__device__ float g_HCA[(size_t)NQ_ * 64];
__device__ float g_HSA[(size_t)NQ_ * 64];
__device__ float g_CA [(size_t)NQ_ * EMB_];
__device__ float g_SA [(size_t)NQ_ * P_];
__device__ float g_PT [(size_t)NQ_ * P_ * 8];       // sx,sy,w0..w3,sa,pad
__device__ __half g_Xh[(size_t)MPAD_ * XDIM_];      // 33.6 MB fp16 X (padded rows)
__device__ __half g_Wt[(size_t)EMB_ * XDIM_];       // 4.2 MB  W_out^T fp16 [N][K]
__device__ float g_PART[(size_t)SK_ * NQ_ * EMB_];  // split-K partials (8 MB)

// ---------------- helpers ----------------
__device__ __forceinline__ uint32_t smem_u32(const void* p) {
    uint32_t a;
    asm("{ .reg .u64 t; cvta.to.shared.u64 t, %1; cvt.u32.u64 %0, t; }" : "=r"(a) : "l"(p));
    return a;
}

__device__ __forceinline__ void cp_async16(uint32_t dst, const void* src) {
    asm volatile("cp.async.cg.shared.global [%0], [%1], 16;" :: "r"(dst), "l"(src));
}
#define CP_COMMIT() asm volatile("cp.async.commit_group;" ::: "memory")
#define CP_WAIT0()  asm volatile("cp.async.wait_group 0;" ::: "memory")

__device__ __forceinline__ void ldmx4(uint32_t* r, uint32_t addr) {
    asm volatile("ldmatrix.sync.aligned.m8n8.x4.shared.b16 {%0,%1,%2,%3}, [%4];"
                 : "=r"(r[0]), "=r"(r[1]), "=r"(r[2]), "=r"(r[3]) : "r"(addr));
}

__device__ __forceinline__ void mma16816(float* c, const uint32_t* a, uint32_t b0, uint32_t b1) {
    asm volatile(
        "mma.sync.aligned.m16n8k16.row.col.f32.f16.f16.f32 "
        "{%0,%1,%2,%3}, {%4,%5,%6,%7}, {%8,%9}, {%0,%1,%2,%3};"
        : "+f"(c[0]), "+f"(c[1]), "+f"(c[2]), "+f"(c[3])
        : "r"(a[0]), "r"(a[1]), "r"(a[2]), "r"(a[3]), "r"(b0), "r"(b1));
}

// ---------------- NCHW -> NHWC transpose (per level) ----------------
__global__ void transpose_cl(const float* __restrict__ in, float* __restrict__ out, int HW)
{
    __shared__ __align__(16) float tile[256][33];
    const int b    = blockIdx.y;
    const int pix0 = blockIdx.x * 32;
    const int tid  = threadIdx.x;
    const int lane = tid & 31, cg = tid >> 5;

    const float* inb = in + (size_t)b * 256 * HW;
#pragma unroll
    for (int c = cg; c < 256; c += 8)
        tile[c][lane] = inb[(size_t)c * HW + pix0 + lane];
    __syncthreads();

    float* outb = out + ((size_t)b * HW + pix0) * 256;
#pragma unroll 8
    for (int pp = 0; pp < 32; ++pp)
        outb[(size_t)pp * 256 + tid] = tile[tid][pp];
}

// ---------------- W_out (8192x256 f32) -> Wt (256x8192 f16) ----------------
__global__ void wt_convert(const float* __restrict__ W, __half* __restrict__ Wt)
{
    __shared__ float tile[32][33];
    const int k0 = blockIdx.x * 32, n0 = blockIdx.y * 32;
    const int tx = threadIdx.x, ty = threadIdx.y;
#pragma unroll
    for (int i = 0; i < 32; i += 8)
        tile[ty + i][tx] = W[(size_t)(k0 + ty + i) * 256 + n0 + tx];
    __syncthreads();
#pragma unroll
    for (int i = 0; i < 32; i += 8)
        Wt[(size_t)(n0 + ty + i) * XDIM_ + k0 + tx] = __float2half(tile[tx][ty + i]);
}

// ---------------- generic small GEMM: C = act(A(MxK) @ W(KxN) [+ bias]) ----------------
__global__ void gemm_small(const float* __restrict__ A, const float* __restrict__ Wm,
                           const float* __restrict__ bias, float* __restrict__ C,
                           int M, int N, int K, int mode)
{
    __shared__ __align__(16) float As[16][68];
    __shared__ __align__(16) float Bs[16][64];
    const int tid = threadIdx.x;
    const int m0 = blockIdx.x * 64, n0 = blockIdx.y * 64;
    const int tx = tid & 15, ty = tid >> 4;

    float acc[4][4] = {};

    const int lm = tid >> 2;
    const int lk = (tid & 3) * 4;
    const int bk = tid >> 4;
    const int bn = (tid & 15) * 4;

    for (int k0 = 0; k0 < K; k0 += 16) {
        float4 av = make_float4(0.f, 0.f, 0.f, 0.f);
        if (m0 + lm < M)
            av = *(const float4*)(A + (size_t)(m0 + lm) * K + k0 + lk);
        As[lk + 0][lm] = av.x; As[lk + 1][lm] = av.y;
        As[lk + 2][lm] = av.z; As[lk + 3][lm] = av.w;

        float4 bv = *(const float4*)(Wm + (size_t)(k0 + bk) * N + n0 + bn);
        *(float4*)&Bs[bk][bn] = bv;
        __syncthreads();

#pragma unroll
        for (int kk = 0; kk < 16; ++kk) {
            float a[4], b[4];
            *(float4*)a = *(const float4*)&As[kk][ty * 4];
            *(float4*)b = *(const float4*)&Bs[kk][tx * 4];
#pragma unroll
            for (int i = 0; i < 4; ++i)
#pragma unroll
                for (int j = 0; j < 4; ++j)
                    acc[i][j] += a[i] * b[j];
        }
        __syncthreads();
    }

#pragma unroll
    for (int i = 0; i < 4; ++i) {
        const int row = m0 + ty * 4 + i;
        if (row >= M) continue;
#pragma unroll
        for (int j = 0; j < 4; ++j) {
            const int col = n0 + tx * 4 + j;
            float v = acc[i][j];
            if (bias) v += bias[col];
            if (mode == 1)       v = fmaxf(v, 0.f);
            else if (mode == 2)  v = 1.f / (1.f + expf(-v));
            C[(size_t)row * N + col] = v;
        }
    }
}

// ---------------- HMMA split-K GEMM: part[kb] = Xh(2048x8192) @ Wt^T ----------------
// grid (16, 2, SK_), 256 threads. CTA tile 128x128, K-chunk 2048, stage BK=64 halves,
// SW128-swizzled smem rows (128B), double-buffered cp.async, mma.m16n8k16 f16->f32.
#define TC_NS 32                       // stages: 2048 / 64
#define TC_SMEM (2 * (16384 + 16384))  // 64 KB

__global__ __launch_bounds__(256, 1) void gemm_mma(const __half* __restrict__ Xh,
                                                   const __half* __restrict__ Wt,
                                                   float* __restrict__ part)
{
    extern __shared__ char dsm[];

    const int tid  = threadIdx.x;
    const int wid  = tid >> 5, lane = tid & 31;
    const int m0   = blockIdx.x * 128;
    const int n0   = blockIdx.y * 128;
    const int kb   = blockIdx.z;
    const int kst  = kb * (XDIM_ / SK_);

    const int wm = wid & 3;   // 0..3 -> m offset wm*32
    const int wn = wid >> 2;  // 0..1 -> n offset wn*64

    const uint32_t sA[2] = { smem_u32(dsm),         smem_u32(dsm + 32768) };
    const uint32_t sB[2] = { smem_u32(dsm + 16384), smem_u32(dsm + 49152) };

    // per-thread load slots: 4 chunks A + 4 chunks B per stage
    const int lrow = tid >> 1;               // 0..127 (two threads per row)
    const int lch0 = (tid & 1) * 4;          // chunks 0..3 or 4..7

    auto issue_stage = [&](int s, int buf) {
        const int gk = kst + s * 64;
        const __half* asrc = Xh + (size_t)(m0 + lrow) * XDIM_ + gk + lch0 * 8;
        const __half* bsrc = Wt + (size_t)(n0 + lrow) * XDIM_ + gk + lch0 * 8;
        const uint32_t arow = sA[buf] + lrow * 128;
        const uint32_t brow = sB[buf] + lrow * 128;
        const int r7 = lrow & 7;
#pragma unroll
        for (int c = 0; c < 4; ++c)
            cp_async16(arow + (((lch0 + c) ^ r7) << 4), asrc + c * 8);
#pragma unroll
        for (int c = 0; c < 4; ++c)
            cp_async16(brow + (((lch0 + c) ^ r7) << 4), bsrc + c * 8);
        CP_COMMIT();
    };

    float c[2][8][4] = {};

    issue_stage(0, 0);

    for (int s = 0; s < TC_NS; ++s) {
        const int cur = s & 1;
        CP_WAIT0();
        __syncthreads();
        if (s + 1 < TC_NS)
            issue_stage(s + 1, cur ^ 1);

        // compute on buffer cur: 4 k16-steps
#pragma unroll
        for (int kk = 0; kk < 4; ++kk) {
            uint32_t a[2][4];
#pragma unroll
            for (int mt = 0; mt < 2; ++mt) {
                const int row = wm * 32 + mt * 16 + (lane & 15);
                const int ch  = kk * 2 + (lane >> 4);
                ldmx4(a[mt], sA[cur] + row * 128 + (((ch ^ (row & 7))) << 4));
            }
            uint32_t b[4][4];
#pragma unroll
            for (int nt2 = 0; nt2 < 4; ++nt2) {
                const int row = wn * 64 + nt2 * 16 + ((lane >> 4) << 3) + (lane & 7);
                const int ch  = kk * 2 + ((lane >> 3) & 1);
                ldmx4(b[nt2], sB[cur] + row * 128 + (((ch ^ (row & 7))) << 4));
            }
#pragma unroll
            for (int mt = 0; mt < 2; ++mt)
#pragma unroll
                for (int nt = 0; nt < 8; ++nt)
                    mma16816(c[mt][nt], a[mt], b[nt >> 1][(nt & 1) * 2], b[nt >> 1][(nt & 1) * 2 + 1]);
        }
        __syncthreads();
    }

    // epilogue: write partials (rows >= NQ_ are padding, skip)
    float* pbase = part + (size_t)kb * NQ_ * EMB_;
    const int g   = lane >> 2;
    const int tg2 = (lane & 3) * 2;
#pragma unroll
    for (int mt = 0; mt < 2; ++mt) {
        const int r0 = m0 + wm * 32 + mt * 16 + g;
        const int r1 = r0 + 8;
#pragma unroll
        for (int nt = 0; nt < 8; ++nt) {
            const int col = n0 + wn * 64 + nt * 8 + tg2;
            if (r0 < NQ_) *(float2*)(pbase + (size_t)r0 * EMB_ + col) = make_float2(c[mt][nt][0], c[mt][nt][1]);
            if (r1 < NQ_) *(float2*)(pbase + (size_t)r1 * EMB_ + col) = make_float2(c[mt][nt][2], c[mt][nt][3]);
        }
    }
}

// ---------------- reduce partials + bias + residual ----------------
__global__ void reduce_out(const float* __restrict__ part, const float* __restrict__ bias,
                           const float* __restrict__ resid, float* __restrict__ out, int total)
{
    const int idx = blockIdx.x * blockDim.x + threadIdx.x;
    if (idx >= total) return;
    float s = 0.f;
#pragma unroll
    for (int kb = 0; kb < SK_; ++kb)
        s += part[(size_t)kb * total + idx];
    out[idx] = s + bias[idx & (EMB_ - 1)] + resid[idx];
}

// ---------------- per-point geometry prep ----------------
__global__ void point_prep(const float* __restrict__ OFF, const float* __restrict__ xyzrt,
                           const float* __restrict__ SA, float* __restrict__ PT)
{
    const int q = blockIdx.x;
    const int p = threadIdx.x;   // 0..127

    const float x  = xyzrt[q * 5 + 0];
    const float y  = xyzrt[q * 5 + 1];
    const float z  = xyzrt[q * 5 + 2];
    const float r  = xyzrt[q * 5 + 3];
    const float th = xyzrt[q * 5 + 4];

    const float ox = OFF[(size_t)q * 384 + p * 3 + 0];
    const float oy = OFF[(size_t)q * 384 + p * 3 + 1];
    const float oz = OFF[(size_t)q * 384 + p * 3 + 2];

    const float rw = exp2f(z - 0.5f * r);
    const float rh = exp2f(z + 0.5f * r);
    float sth, cth;
    sincosf(th, &sth, &cth);

    const float offx = ox * rw;
    const float offy = oy * rh;
    const float sx = x + cth * offx - sth * offy;
    const float sy = y + sth * offx + cth * offy;
    const float sz = z + oz;

    float w[4];
#pragma unroll
    for (int lvl = 0; lvl < 4; ++lvl) {
        const float d = sz - (float)(2 + lvl);
        w[lvl] = 1.f / (1.f + expf(0.5f * d * d));
    }

    float* o = PT + ((size_t)q * P_ + p) * 8;
    float4 o0 = make_float4(sx, sy, w[0], w[1]);
    float4 o1 = make_float4(w[2], w[3], SA[(size_t)q * P_ + p], 0.f);
    *(float4*)o       = o0;
    *(float4*)(o + 4) = o1;
}

// ---------------- bilinear sampler over 4 levels (channel-last) ----------------
__device__ __forceinline__ void samp_lvl(const float* __restrict__ vb, int WW,
                                         float inv, float w, float sx, float sy,
                                         float& a0, float& a1, float& a2, float& a3)
{
    const float ix = sx * inv - 0.5f;
    const float iy = sy * inv - 0.5f;
    const float x0f = floorf(ix), y0f = floorf(iy);
    const float wx1 = ix - x0f, wy1 = iy - y0f;
    const float wx0 = 1.f - wx1, wy0 = 1.f - wy1;
    const int x0 = (int)x0f, y0 = (int)y0f;
    const int x1 = x0 + 1,   y1 = y0 + 1;
    const bool vx0 = (x0 >= 0) & (x0 < WW);
    const bool vx1 = (x1 >= 0) & (x1 < WW);

    if ((y0 >= 0) & (y0 < WW)) {
        const float* row = vb + (size_t)y0 * WW * 256;
        if (vx0) { const float ww = w * wx0 * wy0; const float4 v = *(const float4*)(row + (size_t)x0 * 256);
                   a0 += ww * v.x; a1 += ww * v.y; a2 += ww * v.z; a3 += ww * v.w; }
        if (vx1) { const float ww = w * wx1 * wy0; const float4 v = *(const float4*)(row + (size_t)x1 * 256);
                   a0 += ww * v.x; a1 += ww * v.y; a2 += ww * v.z; a3 += ww * v.w; }
    }
    if ((y1 >= 0) & (y1 < WW)) {
        const float* row = vb + (size_t)y1 * WW * 256;
        if (vx0) { const float ww = w * wx0 * wy1; const float4 v = *(const float4*)(row + (size_t)x0 * 256);
                   a0 += ww * v.x; a1 += ww * v.y; a2 += ww * v.z; a3 += ww * v.w; }
        if (vx1) { const float ww = w * wx1 * wy1; const float4 v = *(const float4*)(row + (size_t)x1 * 256);
                   a0 += ww * v.x; a1 += ww * v.y; a2 += ww * v.z; a3 += ww * v.w; }
    }
}

__global__ void sampler_kernel(const float* __restrict__ PT, const float* __restrict__ CA,
                               __half* __restrict__ X)
{
    const int q   = blockIdx.x;
    const int b   = q / L_;
    const int sub = threadIdx.x >> 4;          // 0..15: point within group
    const int c4  = (threadIdx.x & 15) * 4;    // channel quad within head

#pragma unroll 2
    for (int it = 0; it < 8; ++it) {
        const int p = it * 16 + sub;
        const int g = p >> 5;

        const float* pt = PT + ((size_t)q * P_ + p) * 8;
        const float4 pt0 = *(const float4*)pt;        // sx, sy, w0, w1
        const float4 pt1 = *(const float4*)(pt + 4);  // w2, w3, sa, -
        const float4 ca4 = *(const float4*)(CA + (size_t)q * EMB_ + g * CH_ + c4);

        float a0 = 0.f, a1 = 0.f, a2 = 0.f, a3 = 0.f;
        const float sx = pt0.x, sy = pt0.y;
        const int choff = g * CH_ + c4;

        samp_lvl(g_vt0 + (size_t)b * HW0_ * 256 + choff, 256, 0.25f,    pt0.z, sx, sy, a0, a1, a2, a3);
        samp_lvl(g_vt1 + (size_t)b * HW1_ * 256 + choff, 128, 0.125f,   pt0.w, sx, sy, a0, a1, a2, a3);
        samp_lvl(g_vt2 + (size_t)b * HW2_ * 256 + choff,  64, 0.0625f,  pt1.x, sx, sy, a0, a1, a2, a3);
        samp_lvl(g_vt3 + (size_t)b * HW3_ * 256 + choff,  32, 0.03125f, pt1.y, sx, sy, a0, a1, a2, a3);

        const float sam = pt1.z;
        __half2 h0 = __floats2half2_rn(a0 * ca4.x * sam, a1 * ca4.y * sam);
        __half2 h1 = __floats2half2_rn(a2 * ca4.z * sam, a3 * ca4.w * sam);
        uint2 o;
        o.x = *(uint32_t*)&h0;
        o.y = *(uint32_t*)&h1;
        *(uint2*)(X + (size_t)q * XDIM_ + p * CH_ + c4) = o;
    }
}

// ---------------- launch ----------------
static void* sym_addr(const void* symbol)
{
    void* p = nullptr;
    cudaGetSymbolAddress(&p, symbol);
    return p;
}

extern "C" void kernel_launch(void* const* d_in, const int* in_sizes, int n_in,
                              void* d_out, int out_size)
{
    const float* v0    = (const float*)d_in[0];
    const float* v1    = (const float*)d_in[1];
    const float* v2    = (const float*)d_in[2];
    const float* v3    = (const float*)d_in[3];
    const float* qc    = (const float*)d_in[4];
    const float* xyzrt = (const float*)d_in[5];
    // d_in[6] strides (int32) -- fixed [4,8,16,32], folded into constants
    const float* W_off = (const float*)d_in[7];
    const float* b_off = (const float*)d_in[8];
    const float* W_ca1 = (const float*)d_in[9];
    const float* W_ca2 = (const float*)d_in[10];
    const float* W_sa1 = (const float*)d_in[11];
    const float* W_sa2 = (const float*)d_in[12];
    const float* W_out = (const float*)d_in[13];
    const float* b_out = (const float*)d_in[14];
    float* out = (float*)d_out;

    float*  p_vt0 = (float*)sym_addr(g_vt0);
    float*  p_vt1 = (float*)sym_addr(g_vt1);
    float*  p_vt2 = (float*)sym_addr(g_vt2);
    float*  p_vt3 = (float*)sym_addr(g_vt3);
    float*  p_OFF = (float*)sym_addr(g_OFF);
    float*  p_HCA = (float*)sym_addr(g_HCA);
    float*  p_HSA = (float*)sym_addr(g_HSA);
    float*  p_CA  = (float*)sym_addr(g_CA);
    float*  p_SA  = (float*)sym_addr(g_SA);
    float*  p_PT  = (float*)sym_addr(g_PT);
    __half* p_Xh  = (__half*)sym_addr(g_Xh);
    __half* p_Wt  = (__half*)sym_addr(g_Wt);
    float*  p_PRT = (float*)sym_addr(g_PART);

    static bool attr_done = false;
    if (!attr_done) {
        cudaFuncSetAttribute(gemm_mma, cudaFuncAttributeMaxDynamicSharedMemorySize, TC_SMEM);
        attr_done = true;
    }

    // 1) NCHW -> NHWC for all 4 levels + W_out transpose/convert
    transpose_cl<<<dim3(HW0_ / 32, B_), 256>>>(v0, p_vt0, HW0_);
    transpose_cl<<<dim3(HW1_ / 32, B_), 256>>>(v1, p_vt1, HW1_);
    transpose_cl<<<dim3(HW2_ / 32, B_), 256>>>(v2, p_vt2, HW2_);
    transpose_cl<<<dim3(HW3_ / 32, B_), 256>>>(v3, p_vt3, HW3_);
    wt_convert<<<dim3(XDIM_ / 32, EMB_ / 32), dim3(32, 8)>>>(W_out, p_Wt);

    const int gm = (NQ_ + 63) / 64;  // 32

    // 2) projections
    gemm_small<<<dim3(gm, 384 / 64), 256>>>(qc, W_off, b_off, p_OFF, NQ_, 384, EMB_, 0);
    gemm_small<<<dim3(gm, 1),        256>>>(qc, W_ca1, nullptr, p_HCA, NQ_, 64,  EMB_, 1);
    gemm_small<<<dim3(gm, 256 / 64), 256>>>(p_HCA, W_ca2, nullptr, p_CA, NQ_, 256, 64, 2);
    gemm_small<<<dim3(gm, 1),        256>>>(qc, W_sa1, nullptr, p_HSA, NQ_, 64,  EMB_, 1);
    gemm_small<<<dim3(gm, 128 / 64), 256>>>(p_HSA, W_sa2, nullptr, p_SA, NQ_, 128, 64, 2);

    // 3) per-point geometry + level weights
    point_prep<<<NQ_, P_>>>(p_OFF, xyzrt, p_SA, p_PT);

    // 4) bilinear sampling + ca*sa scaling -> X fp16 (2000 x 8192)
    sampler_kernel<<<NQ_, 256>>>(p_PT, p_CA, p_Xh);

    // 5) final GEMM on HMMA tensor path: X @ W_out, split-K partials, then reduce
    gemm_mma<<<dim3(MPAD_ / 128, EMB_ / 128, SK_), 256, TC_SMEM>>>(p_Xh, p_Wt, p_PRT);
    reduce_out<<<(NQ_ * EMB_ + 255) / 256, 256>>>(p_PRT, b_out, qc, out, NQ_ * EMB_);
}

// round 4
// speedup vs baseline: 1.8616x; 1.0600x over previous
#include <cuda_runtime.h>
#include <cuda_fp16.h>
#include <math.h>
#include <stdint.h>

// Problem constants (fixed by setup_inputs)
#define B_    2
#define L_    1000
#define NQ_   2000
#define MPAD_ 2048    // padded M for GEMM (no guards on A loads)
#define EMB_  256
#define G_    4
#define NP_   32
#define P_    128     // G_*NP_
#define CH_   64      // EMB_/G_
#define XDIM_ 8192    // P_*CH_

// Level geometry: H=W = 256,128,64,32 ; strides 4,8,16,32
#define HW0_ 65536
#define HW1_ 16384
#define HW2_ 4096
#define HW3_ 1024

#define SK_ 4         // split-K factor for final GEMM
#define WTH_ 1e-4f    // level-weight skip threshold

// ---------------- scratch (device globals; no allocations) ----------------
__device__ __half g_vt0[(size_t)B_ * HW0_ * EMB_];  // 67 MB channel-last fp16
__device__ __half g_vt1[(size_t)B_ * HW1_ * EMB_];  // 16.8 MB
__device__ __half g_vt2[(size_t)B_ * HW2_ * EMB_];  // 4.2 MB
__device__ __half g_vt3[(size_t)B_ * HW3_ * EMB_];  // 1.0 MB
__device__ float g_OFF[(size_t)NQ_ * 384];
__device__ float g_HCA[(size_t)NQ_ * 64];
__device__ float g_HSA[(size_t)NQ_ * 64];
__device__ float g_CA [(size_t)NQ_ * EMB_];
__device__ float g_SA [(size_t)NQ_ * P_];
__device__ float g_PT [(size_t)NQ_ * P_ * 8];       // sx,sy,w0..w3,sa,pad
__device__ __half g_Xh[(size_t)MPAD_ * XDIM_];      // 33.6 MB fp16 X (padded rows)
__device__ __half g_Wt[(size_t)EMB_ * XDIM_];       // 4.2 MB  W_out^T fp16 [N][K]
__device__ float g_PART[(size_t)SK_ * NQ_ * EMB_];  // split-K partials (8 MB)

// ---------------- helpers ----------------
__device__ __forceinline__ uint32_t smem_u32(const void* p) {
    uint32_t a;
    asm("{ .reg .u64 t; cvta.to.shared.u64 t, %1; cvt.u32.u64 %0, t; }" : "=r"(a) : "l"(p));
    return a;
}

__device__ __forceinline__ void cp_async16(uint32_t dst, const void* src) {
    asm volatile("cp.async.cg.shared.global [%0], [%1], 16;" :: "r"(dst), "l"(src));
}
#define CP_COMMIT() asm volatile("cp.async.commit_group;" ::: "memory")
#define CP_WAIT1()  asm volatile("cp.async.wait_group 1;" ::: "memory")

__device__ __forceinline__ void ldmx4(uint32_t* r, uint32_t addr) {
    asm volatile("ldmatrix.sync.aligned.m8n8.x4.shared.b16 {%0,%1,%2,%3}, [%4];"
                 : "=r"(r[0]), "=r"(r[1]), "=r"(r[2]), "=r"(r[3]) : "r"(addr));
}

__device__ __forceinline__ void mma16816(float* c, const uint32_t* a, uint32_t b0, uint32_t b1) {
    asm volatile(
        "mma.sync.aligned.m16n8k16.row.col.f32.f16.f16.f32 "
        "{%0,%1,%2,%3}, {%4,%5,%6,%7}, {%8,%9}, {%0,%1,%2,%3};"
        : "+f"(c[0]), "+f"(c[1]), "+f"(c[2]), "+f"(c[3])
        : "r"(a[0]), "r"(a[1]), "r"(a[2]), "r"(a[3]), "r"(b0), "r"(b1));
}

// ---------------- NCHW f32 -> NHWC f16 transpose (per level) ----------------
__global__ void transpose_cl(const float* __restrict__ in, __half* __restrict__ out, int HW)
{
    __shared__ __align__(16) float tile[256][33];
    const int b    = blockIdx.y;
    const int pix0 = blockIdx.x * 32;
    const int tid  = threadIdx.x;
    const int lane = tid & 31, cg = tid >> 5;

    const float* inb = in + (size_t)b * 256 * HW;
#pragma unroll
    for (int c = cg; c < 256; c += 8)
        tile[c][lane] = inb[(size_t)c * HW + pix0 + lane];
    __syncthreads();

    __half* outb = out + ((size_t)b * HW + pix0) * 256;
    const int pair = tid & 127;          // channel pair 0..127
    const int hp   = tid >> 7;           // 0..1
#pragma unroll 8
    for (int pp = 0; pp < 16; ++pp) {
        const int pix = pp * 2 + hp;
        __half2 h = __floats2half2_rn(tile[pair * 2][pix], tile[pair * 2 + 1][pix]);
        *(__half2*)(outb + (size_t)pix * 256 + pair * 2) = h;
    }
}

// ---------------- W_out (8192x256 f32) -> Wt (256x8192 f16) ----------------
__global__ void wt_convert(const float* __restrict__ W, __half* __restrict__ Wt)
{
    __shared__ float tile[32][33];
    const int k0 = blockIdx.x * 32, n0 = blockIdx.y * 32;
    const int tx = threadIdx.x, ty = threadIdx.y;
#pragma unroll
    for (int i = 0; i < 32; i += 8)
        tile[ty + i][tx] = W[(size_t)(k0 + ty + i) * 256 + n0 + tx];
    __syncthreads();
#pragma unroll
    for (int i = 0; i < 32; i += 8)
        Wt[(size_t)(n0 + ty + i) * XDIM_ + k0 + tx] = __float2half(tile[tx][ty + i]);
}

// ---------------- generic small GEMM: C = act(A(MxK) @ W(KxN) [+ bias]) ----------------
__global__ void gemm_small(const float* __restrict__ A, const float* __restrict__ Wm,
                           const float* __restrict__ bias, float* __restrict__ C,
                           int M, int N, int K, int mode)
{
    __shared__ __align__(16) float As[16][68];
    __shared__ __align__(16) float Bs[16][64];
    const int tid = threadIdx.x;
    const int m0 = blockIdx.x * 64, n0 = blockIdx.y * 64;
    const int tx = tid & 15, ty = tid >> 4;

    float acc[4][4] = {};

    const int lm = tid >> 2;
    const int lk = (tid & 3) * 4;
    const int bk = tid >> 4;
    const int bn = (tid & 15) * 4;

    for (int k0 = 0; k0 < K; k0 += 16) {
        float4 av = make_float4(0.f, 0.f, 0.f, 0.f);
        if (m0 + lm < M)
            av = *(const float4*)(A + (size_t)(m0 + lm) * K + k0 + lk);
        As[lk + 0][lm] = av.x; As[lk + 1][lm] = av.y;
        As[lk + 2][lm] = av.z; As[lk + 3][lm] = av.w;

        float4 bv = *(const float4*)(Wm + (size_t)(k0 + bk) * N + n0 + bn);
        *(float4*)&Bs[bk][bn] = bv;
        __syncthreads();

#pragma unroll
        for (int kk = 0; kk < 16; ++kk) {
            float a[4], b[4];
            *(float4*)a = *(const float4*)&As[kk][ty * 4];
            *(float4*)b = *(const float4*)&Bs[kk][tx * 4];
#pragma unroll
            for (int i = 0; i < 4; ++i)
#pragma unroll
                for (int j = 0; j < 4; ++j)
                    acc[i][j] += a[i] * b[j];
        }
        __syncthreads();
    }

#pragma unroll
    for (int i = 0; i < 4; ++i) {
        const int row = m0 + ty * 4 + i;
        if (row >= M) continue;
#pragma unroll
        for (int j = 0; j < 4; ++j) {
            const int col = n0 + tx * 4 + j;
            float v = acc[i][j];
            if (bias) v += bias[col];
            if (mode == 1)       v = fmaxf(v, 0.f);
            else if (mode == 2)  v = 1.f / (1.f + expf(-v));
            C[(size_t)row * N + col] = v;
        }
    }
}

// ---------------- HMMA split-K GEMM: part[kb] = Xh(2048x8192) @ Wt^T ----------------
// grid (16, 2, SK_), 256 threads. CTA tile 128x128, K-chunk 2048, stage BK=64 halves,
// SW128-swizzled smem rows (128B), 3-stage cp.async pipeline, mma.m16n8k16 f16->f32.
#define TC_NS 32                       // stages: 2048 / 64
#define TC_SMEM (3 * (16384 + 16384))  // 96 KB

__global__ __launch_bounds__(256, 1) void gemm_mma(const __half* __restrict__ Xh,
                                                   const __half* __restrict__ Wt,
                                                   float* __restrict__ part)
{
    extern __shared__ char dsm[];

    const int tid  = threadIdx.x;
    const int wid  = tid >> 5, lane = tid & 31;
    const int m0   = blockIdx.x * 128;
    const int n0   = blockIdx.y * 128;
    const int kb   = blockIdx.z;
    const int kst  = kb * (XDIM_ / SK_);

    const int wm = wid & 3;   // 0..3 -> m offset wm*32
    const int wn = wid >> 2;  // 0..1 -> n offset wn*64

    uint32_t sA[3], sB[3];
#pragma unroll
    for (int i = 0; i < 3; ++i) {
        sA[i] = smem_u32(dsm + i * 32768);
        sB[i] = smem_u32(dsm + i * 32768 + 16384);
    }

    // per-thread load slots: 4 chunks A + 4 chunks B per stage
    const int lrow = tid >> 1;               // 0..127 (two threads per row)
    const int lch0 = (tid & 1) * 4;          // chunks 0..3 or 4..7

    auto issue_stage = [&](int s) {
        const int buf = s % 3;
        const int gk = kst + s * 64;
        const __half* asrc = Xh + (size_t)(m0 + lrow) * XDIM_ + gk + lch0 * 8;
        const __half* bsrc = Wt + (size_t)(n0 + lrow) * XDIM_ + gk + lch0 * 8;
        const uint32_t arow = sA[buf] + lrow * 128;
        const uint32_t brow = sB[buf] + lrow * 128;
        const int r7 = lrow & 7;
#pragma unroll
        for (int c = 0; c < 4; ++c)
            cp_async16(arow + (((lch0 + c) ^ r7) << 4), asrc + c * 8);
#pragma unroll
        for (int c = 0; c < 4; ++c)
            cp_async16(brow + (((lch0 + c) ^ r7) << 4), bsrc + c * 8);
        CP_COMMIT();
    };

    float c[2][8][4] = {};

    issue_stage(0);
    issue_stage(1);

    for (int s = 0; s < TC_NS; ++s) {
        const int cur = s % 3;
        CP_WAIT1();
        __syncthreads();
        if (s + 2 < TC_NS)
            issue_stage(s + 2);

        // compute on buffer cur: 4 k16-steps
#pragma unroll
        for (int kk = 0; kk < 4; ++kk) {
            uint32_t a[2][4];
#pragma unroll
            for (int mt = 0; mt < 2; ++mt) {
                const int row = wm * 32 + mt * 16 + (lane & 15);
                const int ch  = kk * 2 + (lane >> 4);
                ldmx4(a[mt], sA[cur] + row * 128 + (((ch ^ (row & 7))) << 4));
            }
            uint32_t b[4][4];
#pragma unroll
            for (int nt2 = 0; nt2 < 4; ++nt2) {
                const int row = wn * 64 + nt2 * 16 + ((lane >> 4) << 3) + (lane & 7);
                const int ch  = kk * 2 + ((lane >> 3) & 1);
                ldmx4(b[nt2], sB[cur] + row * 128 + (((ch ^ (row & 7))) << 4));
            }
#pragma unroll
            for (int mt = 0; mt < 2; ++mt)
#pragma unroll
                for (int nt = 0; nt < 8; ++nt)
                    mma16816(c[mt][nt], a[mt], b[nt >> 1][(nt & 1) * 2], b[nt >> 1][(nt & 1) * 2 + 1]);
        }
        __syncthreads();
    }

    // epilogue: write partials (rows >= NQ_ are padding, skip)
    float* pbase = part + (size_t)kb * NQ_ * EMB_;
    const int g   = lane >> 2;
    const int tg2 = (lane & 3) * 2;
#pragma unroll
    for (int mt = 0; mt < 2; ++mt) {
        const int r0 = m0 + wm * 32 + mt * 16 + g;
        const int r1 = r0 + 8;
#pragma unroll
        for (int nt = 0; nt < 8; ++nt) {
            const int col = n0 + wn * 64 + nt * 8 + tg2;
            if (r0 < NQ_) *(float2*)(pbase + (size_t)r0 * EMB_ + col) = make_float2(c[mt][nt][0], c[mt][nt][1]);
            if (r1 < NQ_) *(float2*)(pbase + (size_t)r1 * EMB_ + col) = make_float2(c[mt][nt][2], c[mt][nt][3]);
        }
    }
}

// ---------------- reduce partials + bias + residual ----------------
__global__ void reduce_out(const float* __restrict__ part, const float* __restrict__ bias,
                           const float* __restrict__ resid, float* __restrict__ out, int total)
{
    const int idx = blockIdx.x * blockDim.x + threadIdx.x;
    if (idx >= total) return;
    float s = 0.f;
#pragma unroll
    for (int kb = 0; kb < SK_; ++kb)
        s += part[(size_t)kb * total + idx];
    out[idx] = s + bias[idx & (EMB_ - 1)] + resid[idx];
}

// ---------------- per-point geometry prep ----------------
__global__ void point_prep(const float* __restrict__ OFF, const float* __restrict__ xyzrt,
                           const float* __restrict__ SA, float* __restrict__ PT)
{
    const int q = blockIdx.x;
    const int p = threadIdx.x;   // 0..127

    const float x  = xyzrt[q * 5 + 0];
    const float y  = xyzrt[q * 5 + 1];
    const float z  = xyzrt[q * 5 + 2];
    const float r  = xyzrt[q * 5 + 3];
    const float th = xyzrt[q * 5 + 4];

    const float ox = OFF[(size_t)q * 384 + p * 3 + 0];
    const float oy = OFF[(size_t)q * 384 + p * 3 + 1];
    const float oz = OFF[(size_t)q * 384 + p * 3 + 2];

    const float rw = exp2f(z - 0.5f * r);
    const float rh = exp2f(z + 0.5f * r);
    float sth, cth;
    sincosf(th, &sth, &cth);

    const float offx = ox * rw;
    const float offy = oy * rh;
    const float sx = x + cth * offx - sth * offy;
    const float sy = y + sth * offx + cth * offy;
    const float sz = z + oz;

    float w[4];
#pragma unroll
    for (int lvl = 0; lvl < 4; ++lvl) {
        const float d = sz - (float)(2 + lvl);
        w[lvl] = 1.f / (1.f + expf(0.5f * d * d));
    }

    float* o = PT + ((size_t)q * P_ + p) * 8;
    float4 o0 = make_float4(sx, sy, w[0], w[1]);
    float4 o1 = make_float4(w[2], w[3], SA[(size_t)q * P_ + p], 0.f);
    *(float4*)o       = o0;
    *(float4*)(o + 4) = o1;
}

// ---------------- bilinear sampler over 4 levels (fp16 channel-last) ----------------
// 8 threads per point, 8 channels (one uint4) per thread per tap.
__device__ __forceinline__ void samp8(const __half* __restrict__ vb, int WW,
                                      float inv, float w, float sx, float sy,
                                      float* acc)
{
    const float ix = sx * inv - 0.5f;
    const float iy = sy * inv - 0.5f;
    const float x0f = floorf(ix), y0f = floorf(iy);
    const float wx1 = ix - x0f, wy1 = iy - y0f;
    const float wx0 = 1.f - wx1, wy0 = 1.f - wy1;
    const int x0 = (int)x0f, y0 = (int)y0f;
    const int x1 = x0 + 1,   y1 = y0 + 1;
    const bool vx0 = (x0 >= 0) & (x0 < WW);
    const bool vx1 = (x1 >= 0) & (x1 < WW);
    const bool vy0 = (y0 >= 0) & (y0 < WW);
    const bool vy1 = (y1 >= 0) & (y1 < WW);

#define TAP8(xc, yc, wgt)                                                        \
    do {                                                                         \
        const uint4 v = *(const uint4*)(vb + ((size_t)(yc) * WW + (xc)) * 256);  \
        const __half2* h = (const __half2*)&v;                                   \
        const float ww = (wgt);                                                  \
        float2 f0 = __half22float2(h[0]);                                        \
        float2 f1 = __half22float2(h[1]);                                        \
        float2 f2 = __half22float2(h[2]);                                        \
        float2 f3 = __half22float2(h[3]);                                        \
        acc[0] += ww * f0.x; acc[1] += ww * f0.y;                                \
        acc[2] += ww * f1.x; acc[3] += ww * f1.y;                                \
        acc[4] += ww * f2.x; acc[5] += ww * f2.y;                                \
        acc[6] += ww * f3.x; acc[7] += ww * f3.y;                                \
    } while (0)

    if (vy0) {
        if (vx0) TAP8(x0, y0, w * wx0 * wy0);
        if (vx1) TAP8(x1, y0, w * wx1 * wy0);
    }
    if (vy1) {
        if (vx0) TAP8(x0, y1, w * wx0 * wy1);
        if (vx1) TAP8(x1, y1, w * wx1 * wy1);
    }
#undef TAP8
}

__global__ void sampler_kernel(const float* __restrict__ PT, const float* __restrict__ CA,
                               __half* __restrict__ X)
{
    const int q    = blockIdx.x;
    const int b    = q / L_;
    const int pgrp = threadIdx.x >> 3;        // 0..31: point within group of 32
    const int c8   = (threadIdx.x & 7) * 8;   // channel octet within head

#pragma unroll
    for (int it = 0; it < 4; ++it) {
        const int p = it * 32 + pgrp;
        const int g = p >> 5;
        const int choff = g * CH_ + c8;

        const float* pt = PT + ((size_t)q * P_ + p) * 8;
        const float4 pt0 = *(const float4*)pt;        // sx, sy, w0, w1
        const float4 pt1 = *(const float4*)(pt + 4);  // w2, w3, sa, -

        float acc[8] = {};
        const float sx = pt0.x, sy = pt0.y;

        if (pt0.z > WTH_) samp8(g_vt0 + (size_t)b * HW0_ * 256 + choff, 256, 0.25f,    pt0.z, sx, sy, acc);
        if (pt0.w > WTH_) samp8(g_vt1 + (size_t)b * HW1_ * 256 + choff, 128, 0.125f,   pt0.w, sx, sy, acc);
        if (pt1.x > WTH_) samp8(g_vt2 + (size_t)b * HW2_ * 256 + choff,  64, 0.0625f,  pt1.x, sx, sy, acc);
        if (pt1.y > WTH_) samp8(g_vt3 + (size_t)b * HW3_ * 256 + choff,  32, 0.03125f, pt1.y, sx, sy, acc);

        const float sam = pt1.z;
        const float4 ca0 = *(const float4*)(CA + (size_t)q * EMB_ + choff);
        const float4 ca1 = *(const float4*)(CA + (size_t)q * EMB_ + choff + 4);

        __half2 h0 = __floats2half2_rn(acc[0] * ca0.x * sam, acc[1] * ca0.y * sam);
        __half2 h1 = __floats2half2_rn(acc[2] * ca0.z * sam, acc[3] * ca0.w * sam);
        __half2 h2 = __floats2half2_rn(acc[4] * ca1.x * sam, acc[5] * ca1.y * sam);
        __half2 h3 = __floats2half2_rn(acc[6] * ca1.z * sam, acc[7] * ca1.w * sam);
        uint4 o;
        o.x = *(uint32_t*)&h0; o.y = *(uint32_t*)&h1;
        o.z = *(uint32_t*)&h2; o.w = *(uint32_t*)&h3;
        *(uint4*)(X + (size_t)q * XDIM_ + p * CH_ + c8) = o;
    }
}

// ---------------- launch ----------------
static void* sym_addr(const void* symbol)
{
    void* p = nullptr;
    cudaGetSymbolAddress(&p, symbol);
    return p;
}

extern "C" void kernel_launch(void* const* d_in, const int* in_sizes, int n_in,
                              void* d_out, int out_size)
{
    const float* v0    = (const float*)d_in[0];
    const float* v1    = (const float*)d_in[1];
    const float* v2    = (const float*)d_in[2];
    const float* v3    = (const float*)d_in[3];
    const float* qc    = (const float*)d_in[4];
    const float* xyzrt = (const float*)d_in[5];
    // d_in[6] strides (int32) -- fixed [4,8,16,32], folded into constants
    const float* W_off = (const float*)d_in[7];
    const float* b_off = (const float*)d_in[8];
    const float* W_ca1 = (const float*)d_in[9];
    const float* W_ca2 = (const float*)d_in[10];
    const float* W_sa1 = (const float*)d_in[11];
    const float* W_sa2 = (const float*)d_in[12];
    const float* W_out = (const float*)d_in[13];
    const float* b_out = (const float*)d_in[14];
    float* out = (float*)d_out;

    __half* p_vt0 = (__half*)sym_addr(g_vt0);
    __half* p_vt1 = (__half*)sym_addr(g_vt1);
    __half* p_vt2 = (__half*)sym_addr(g_vt2);
    __half* p_vt3 = (__half*)sym_addr(g_vt3);
    float*  p_OFF = (float*)sym_addr(g_OFF);
    float*  p_HCA = (float*)sym_addr(g_HCA);
    float*  p_HSA = (float*)sym_addr(g_HSA);
    float*  p_CA  = (float*)sym_addr(g_CA);
    float*  p_SA  = (float*)sym_addr(g_SA);
    float*  p_PT  = (float*)sym_addr(g_PT);
    __half* p_Xh  = (__half*)sym_addr(g_Xh);
    __half* p_Wt  = (__half*)sym_addr(g_Wt);
    float*  p_PRT = (float*)sym_addr(g_PART);

    static bool attr_done = false;
    if (!attr_done) {
        cudaFuncSetAttribute(gemm_mma, cudaFuncAttributeMaxDynamicSharedMemorySize, TC_SMEM);
        attr_done = true;
    }

    // 1) NCHW f32 -> NHWC f16 for all 4 levels + W_out transpose/convert
    transpose_cl<<<dim3(HW0_ / 32, B_), 256>>>(v0, p_vt0, HW0_);
    transpose_cl<<<dim3(HW1_ / 32, B_), 256>>>(v1, p_vt1, HW1_);
    transpose_cl<<<dim3(HW2_ / 32, B_), 256>>>(v2, p_vt2, HW2_);
    transpose_cl<<<dim3(HW3_ / 32, B_), 256>>>(v3, p_vt3, HW3_);
    wt_convert<<<dim3(XDIM_ / 32, EMB_ / 32), dim3(32, 8)>>>(W_out, p_Wt);

    const int gm = (NQ_ + 63) / 64;  // 32

    // 2) projections
    gemm_small<<<dim3(gm, 384 / 64), 256>>>(qc, W_off, b_off, p_OFF, NQ_, 384, EMB_, 0);
    gemm_small<<<dim3(gm, 1),        256>>>(qc, W_ca1, nullptr, p_HCA, NQ_, 64,  EMB_, 1);
    gemm_small<<<dim3(gm, 256 / 64), 256>>>(p_HCA, W_ca2, nullptr, p_CA, NQ_, 256, 64, 2);
    gemm_small<<<dim3(gm, 1),        256>>>(qc, W_sa1, nullptr, p_HSA, NQ_, 64,  EMB_, 1);
    gemm_small<<<dim3(gm, 128 / 64), 256>>>(p_HSA, W_sa2, nullptr, p_SA, NQ_, 128, 64, 2);

    // 3) per-point geometry + level weights
    point_prep<<<NQ_, P_>>>(p_OFF, xyzrt, p_SA, p_PT);

    // 4) bilinear sampling + ca*sa scaling -> X fp16 (2000 x 8192)
    sampler_kernel<<<NQ_, 256>>>(p_PT, p_CA, p_Xh);

    // 5) final GEMM on HMMA tensor path: X @ W_out, split-K partials, then reduce
    gemm_mma<<<dim3(MPAD_ / 128, EMB_ / 128, SK_), 256, TC_SMEM>>>(p_Xh, p_Wt, p_PRT);
    reduce_out<<<(NQ_ * EMB_ + 255) / 256, 256>>>(p_PRT, b_out, qc, out, NQ_ * EMB_);
}

// round 5
// speedup vs baseline: 2.1937x; 1.1784x over previous
#include <cuda_runtime.h>
#include <cuda_fp16.h>
#include <math.h>
#include <stdint.h>

// Problem constants (fixed by setup_inputs)
#define B_    2
#define L_    1000
#define NQ_   2000
#define MPAD_ 2048    // padded M for GEMM (no guards on A loads)
#define EMB_  256
#define G_    4
#define NP_   32
#define P_    128     // G_*NP_
#define CH_   64      // EMB_/G_
#define XDIM_ 8192    // P_*CH_

// Level geometry: H=W = 256,128,64,32 ; strides 4,8,16,32
#define HW0_ 65536
#define HW1_ 16384
#define HW2_ 4096
#define HW3_ 1024

#define SK_ 4         // split-K factor for final GEMM

// ---------------- scratch (device globals; no allocations) ----------------
__device__ __half g_vt0[(size_t)B_ * HW0_ * EMB_];  // 67 MB channel-last fp16
__device__ __half g_vt1[(size_t)B_ * HW1_ * EMB_];  // 16.8 MB
__device__ __half g_vt2[(size_t)B_ * HW2_ * EMB_];  // 4.2 MB
__device__ __half g_vt3[(size_t)B_ * HW3_ * EMB_];  // 1.0 MB
__device__ float g_OFF[(size_t)NQ_ * 384];
__device__ float g_HCA[(size_t)NQ_ * 64];
__device__ float g_HSA[(size_t)NQ_ * 64];
__device__ float g_CA [(size_t)NQ_ * EMB_];
__device__ float g_SA [(size_t)NQ_ * P_];
__device__ float g_PT [(size_t)NQ_ * P_ * 8];       // sx,sy,w0..w3,sa,pad
__device__ __half g_Xh[(size_t)MPAD_ * XDIM_];      // 33.6 MB fp16 X (padded rows)
__device__ __half g_Wt[(size_t)EMB_ * XDIM_];       // 4.2 MB  W_out^T fp16 [N][K]
__device__ float g_PART[(size_t)SK_ * NQ_ * EMB_];  // split-K partials (8 MB)

// ---------------- helpers ----------------
__device__ __forceinline__ uint32_t smem_u32(const void* p) {
    uint32_t a;
    asm("{ .reg .u64 t; cvta.to.shared.u64 t, %1; cvt.u32.u64 %0, t; }" : "=r"(a) : "l"(p));
    return a;
}

__device__ __forceinline__ void cp_async16(uint32_t dst, const void* src) {
    asm volatile("cp.async.cg.shared.global [%0], [%1], 16;" :: "r"(dst), "l"(src));
}
#define CP_COMMIT() asm volatile("cp.async.commit_group;" ::: "memory")
#define CP_WAIT1()  asm volatile("cp.async.wait_group 1;" ::: "memory")

__device__ __forceinline__ void ldmx4(uint32_t* r, uint32_t addr) {
    asm volatile("ldmatrix.sync.aligned.m8n8.x4.shared.b16 {%0,%1,%2,%3}, [%4];"
                 : "=r"(r[0]), "=r"(r[1]), "=r"(r[2]), "=r"(r[3]) : "r"(addr));
}

__device__ __forceinline__ void mma16816(float* c, const uint32_t* a, uint32_t b0, uint32_t b1) {
    asm volatile(
        "mma.sync.aligned.m16n8k16.row.col.f32.f16.f16.f32 "
        "{%0,%1,%2,%3}, {%4,%5,%6,%7}, {%8,%9}, {%0,%1,%2,%3};"
        : "+f"(c[0]), "+f"(c[1]), "+f"(c[2]), "+f"(c[3])
        : "r"(a[0]), "r"(a[1]), "r"(a[2]), "r"(a[3]), "r"(b0), "r"(b1));
}

// ---------------- NCHW f32 -> NHWC f16 transpose (per level) ----------------
__global__ void transpose_cl(const float* __restrict__ in, __half* __restrict__ out, int HW)
{
    __shared__ __align__(16) float tile[256][33];
    const int b    = blockIdx.y;
    const int pix0 = blockIdx.x * 32;
    const int tid  = threadIdx.x;
    const int lane = tid & 31, cg = tid >> 5;

    const float* inb = in + (size_t)b * 256 * HW;
#pragma unroll
    for (int c = cg; c < 256; c += 8)
        tile[c][lane] = inb[(size_t)c * HW + pix0 + lane];
    __syncthreads();

    __half* outb = out + ((size_t)b * HW + pix0) * 256;
    const int pair = tid & 127;          // channel pair 0..127
    const int hp   = tid >> 7;           // 0..1
#pragma unroll 8
    for (int pp = 0; pp < 16; ++pp) {
        const int pix = pp * 2 + hp;
        __half2 h = __floats2half2_rn(tile[pair * 2][pix], tile[pair * 2 + 1][pix]);
        *(__half2*)(outb + (size_t)pix * 256 + pair * 2) = h;
    }
}

// ---------------- W_out (8192x256 f32) -> Wt (256x8192 f16) ----------------
__global__ void wt_convert(const float* __restrict__ W, __half* __restrict__ Wt)
{
    __shared__ float tile[32][33];
    const int k0 = blockIdx.x * 32, n0 = blockIdx.y * 32;
    const int tx = threadIdx.x, ty = threadIdx.y;
#pragma unroll
    for (int i = 0; i < 32; i += 8)
        tile[ty + i][tx] = W[(size_t)(k0 + ty + i) * 256 + n0 + tx];
    __syncthreads();
#pragma unroll
    for (int i = 0; i < 32; i += 8)
        Wt[(size_t)(n0 + ty + i) * XDIM_ + k0 + tx] = __float2half(tile[tx][ty + i]);
}

// ---------------- generic small GEMM: C = act(A(MxK) @ W(KxN) [+ bias]) ----------------
__global__ void gemm_small(const float* __restrict__ A, const float* __restrict__ Wm,
                           const float* __restrict__ bias, float* __restrict__ C,
                           int M, int N, int K, int mode)
{
    __shared__ __align__(16) float As[16][68];
    __shared__ __align__(16) float Bs[16][64];
    const int tid = threadIdx.x;
    const int m0 = blockIdx.x * 64, n0 = blockIdx.y * 64;
    const int tx = tid & 15, ty = tid >> 4;

    float acc[4][4] = {};

    const int lm = tid >> 2;
    const int lk = (tid & 3) * 4;
    const int bk = tid >> 4;
    const int bn = (tid & 15) * 4;

    for (int k0 = 0; k0 < K; k0 += 16) {
        float4 av = make_float4(0.f, 0.f, 0.f, 0.f);
        if (m0 + lm < M)
            av = *(const float4*)(A + (size_t)(m0 + lm) * K + k0 + lk);
        As[lk + 0][lm] = av.x; As[lk + 1][lm] = av.y;
        As[lk + 2][lm] = av.z; As[lk + 3][lm] = av.w;

        float4 bv = *(const float4*)(Wm + (size_t)(k0 + bk) * N + n0 + bn);
        *(float4*)&Bs[bk][bn] = bv;
        __syncthreads();

#pragma unroll
        for (int kk = 0; kk < 16; ++kk) {
            float a[4], b[4];
            *(float4*)a = *(const float4*)&As[kk][ty * 4];
            *(float4*)b = *(const float4*)&Bs[kk][tx * 4];
#pragma unroll
            for (int i = 0; i < 4; ++i)
#pragma unroll
                for (int j = 0; j < 4; ++j)
                    acc[i][j] += a[i] * b[j];
        }
        __syncthreads();
    }

#pragma unroll
    for (int i = 0; i < 4; ++i) {
        const int row = m0 + ty * 4 + i;
        if (row >= M) continue;
#pragma unroll
        for (int j = 0; j < 4; ++j) {
            const int col = n0 + tx * 4 + j;
            float v = acc[i][j];
            if (bias) v += bias[col];
            if (mode == 1)       v = fmaxf(v, 0.f);
            else if (mode == 2)  v = 1.f / (1.f + expf(-v));
            C[(size_t)row * N + col] = v;
        }
    }
}

// ---------------- HMMA split-K GEMM: part[kb] = Xh(2048x8192) @ Wt^T ----------------
#define TC_NS 32                       // stages: 2048 / 64
#define TC_SMEM (3 * (16384 + 16384))  // 96 KB

__global__ __launch_bounds__(256, 1) void gemm_mma(const __half* __restrict__ Xh,
                                                   const __half* __restrict__ Wt,
                                                   float* __restrict__ part)
{
    extern __shared__ char dsm[];

    const int tid  = threadIdx.x;
    const int wid  = tid >> 5, lane = tid & 31;
    const int m0   = blockIdx.x * 128;
    const int n0   = blockIdx.y * 128;
    const int kb   = blockIdx.z;
    const int kst  = kb * (XDIM_ / SK_);

    const int wm = wid & 3;   // 0..3 -> m offset wm*32
    const int wn = wid >> 2;  // 0..1 -> n offset wn*64

    uint32_t sA[3], sB[3];
#pragma unroll
    for (int i = 0; i < 3; ++i) {
        sA[i] = smem_u32(dsm + i * 32768);
        sB[i] = smem_u32(dsm + i * 32768 + 16384);
    }

    const int lrow = tid >> 1;               // 0..127 (two threads per row)
    const int lch0 = (tid & 1) * 4;          // chunks 0..3 or 4..7

    auto issue_stage = [&](int s) {
        const int buf = s % 3;
        const int gk = kst + s * 64;
        const __half* asrc = Xh + (size_t)(m0 + lrow) * XDIM_ + gk + lch0 * 8;
        const __half* bsrc = Wt + (size_t)(n0 + lrow) * XDIM_ + gk + lch0 * 8;
        const uint32_t arow = sA[buf] + lrow * 128;
        const uint32_t brow = sB[buf] + lrow * 128;
        const int r7 = lrow & 7;
#pragma unroll
        for (int c = 0; c < 4; ++c)
            cp_async16(arow + (((lch0 + c) ^ r7) << 4), asrc + c * 8);
#pragma unroll
        for (int c = 0; c < 4; ++c)
            cp_async16(brow + (((lch0 + c) ^ r7) << 4), bsrc + c * 8);
        CP_COMMIT();
    };

    float c[2][8][4] = {};

    issue_stage(0);
    issue_stage(1);

    for (int s = 0; s < TC_NS; ++s) {
        const int cur = s % 3;
        CP_WAIT1();
        __syncthreads();
        if (s + 2 < TC_NS)
            issue_stage(s + 2);

#pragma unroll
        for (int kk = 0; kk < 4; ++kk) {
            uint32_t a[2][4];
#pragma unroll
            for (int mt = 0; mt < 2; ++mt) {
                const int row = wm * 32 + mt * 16 + (lane & 15);
                const int ch  = kk * 2 + (lane >> 4);
                ldmx4(a[mt], sA[cur] + row * 128 + (((ch ^ (row & 7))) << 4));
            }
            uint32_t b[4][4];
#pragma unroll
            for (int nt2 = 0; nt2 < 4; ++nt2) {
                const int row = wn * 64 + nt2 * 16 + ((lane >> 4) << 3) + (lane & 7);
                const int ch  = kk * 2 + ((lane >> 3) & 1);
                ldmx4(b[nt2], sB[cur] + row * 128 + (((ch ^ (row & 7))) << 4));
            }
#pragma unroll
            for (int mt = 0; mt < 2; ++mt)
#pragma unroll
                for (int nt = 0; nt < 8; ++nt)
                    mma16816(c[mt][nt], a[mt], b[nt >> 1][(nt & 1) * 2], b[nt >> 1][(nt & 1) * 2 + 1]);
        }
        __syncthreads();
    }

    float* pbase = part + (size_t)kb * NQ_ * EMB_;
    const int g   = lane >> 2;
    const int tg2 = (lane & 3) * 2;
#pragma unroll
    for (int mt = 0; mt < 2; ++mt) {
        const int r0 = m0 + wm * 32 + mt * 16 + g;
        const int r1 = r0 + 8;
#pragma unroll
        for (int nt = 0; nt < 8; ++nt) {
            const int col = n0 + wn * 64 + nt * 8 + tg2;
            if (r0 < NQ_) *(float2*)(pbase + (size_t)r0 * EMB_ + col) = make_float2(c[mt][nt][0], c[mt][nt][1]);
            if (r1 < NQ_) *(float2*)(pbase + (size_t)r1 * EMB_ + col) = make_float2(c[mt][nt][2], c[mt][nt][3]);
        }
    }
}

// ---------------- reduce partials + bias + residual ----------------
__global__ void reduce_out(const float* __restrict__ part, const float* __restrict__ bias,
                           const float* __restrict__ resid, float* __restrict__ out, int total)
{
    const int idx = blockIdx.x * blockDim.x + threadIdx.x;
    if (idx >= total) return;
    float s = 0.f;
#pragma unroll
    for (int kb = 0; kb < SK_; ++kb)
        s += part[(size_t)kb * total + idx];
    out[idx] = s + bias[idx & (EMB_ - 1)] + resid[idx];
}

// ---------------- per-point geometry prep ----------------
__global__ void point_prep(const float* __restrict__ OFF, const float* __restrict__ xyzrt,
                           const float* __restrict__ SA, float* __restrict__ PT)
{
    const int q = blockIdx.x;
    const int p = threadIdx.x;   // 0..127

    const float x  = xyzrt[q * 5 + 0];
    const float y  = xyzrt[q * 5 + 1];
    const float z  = xyzrt[q * 5 + 2];
    const float r  = xyzrt[q * 5 + 3];
    const float th = xyzrt[q * 5 + 4];

    const float ox = OFF[(size_t)q * 384 + p * 3 + 0];
    const float oy = OFF[(size_t)q * 384 + p * 3 + 1];
    const float oz = OFF[(size_t)q * 384 + p * 3 + 2];

    const float rw = exp2f(z - 0.5f * r);
    const float rh = exp2f(z + 0.5f * r);
    float sth, cth;
    sincosf(th, &sth, &cth);

    const float offx = ox * rw;
    const float offy = oy * rh;
    const float sx = x + cth * offx - sth * offy;
    const float sy = y + sth * offx + cth * offy;
    const float sz = z + oz;

    float w[4];
#pragma unroll
    for (int lvl = 0; lvl < 4; ++lvl) {
        const float d = sz - (float)(2 + lvl);
        w[lvl] = 1.f / (1.f + expf(0.5f * d * d));
    }

    float* o = PT + ((size_t)q * P_ + p) * 8;
    float4 o0 = make_float4(sx, sy, w[0], w[1]);
    float4 o1 = make_float4(w[2], w[3], SA[(size_t)q * P_ + p], 0.f);
    *(float4*)o       = o0;
    *(float4*)(o + 4) = o1;
}

// ---------------- branchless bilinear sampler over 4 levels (fp16 NHWC) ----------------
// 8 threads per point, 8 channels per thread per tap. All 16 tap loads unconditional:
// coords clamped to valid range, invalid taps get weight 0. Max MLP, no divergence.
__device__ __forceinline__ void acc8(float* acc, uint4 v, float ww)
{
    const __half2* h = (const __half2*)&v;
    float2 f0 = __half22float2(h[0]);
    float2 f1 = __half22float2(h[1]);
    float2 f2 = __half22float2(h[2]);
    float2 f3 = __half22float2(h[3]);
    acc[0] += ww * f0.x; acc[1] += ww * f0.y;
    acc[2] += ww * f1.x; acc[3] += ww * f1.y;
    acc[4] += ww * f2.x; acc[5] += ww * f2.y;
    acc[6] += ww * f3.x; acc[7] += ww * f3.y;
}

__global__ __launch_bounds__(256) void sampler_kernel(const float* __restrict__ PT,
                                                      const float* __restrict__ CA,
                                                      __half* __restrict__ X)
{
    const int q    = blockIdx.x;
    const int b    = q / L_;
    const int pgrp = threadIdx.x >> 3;        // 0..31: point within group of 32
    const int c8   = (threadIdx.x & 7) * 8;   // channel octet within head

    const __half* lb0 = g_vt0 + (size_t)b * HW0_ * 256;
    const __half* lb1 = g_vt1 + (size_t)b * HW1_ * 256;
    const __half* lb2 = g_vt2 + (size_t)b * HW2_ * 256;
    const __half* lb3 = g_vt3 + (size_t)b * HW3_ * 256;

#pragma unroll
    for (int it = 0; it < 4; ++it) {
        const int p = it * 32 + pgrp;
        const int g = p >> 5;
        const int choff = g * CH_ + c8;

        const float* pt = PT + ((size_t)q * P_ + p) * 8;
        const float4 pt0 = *(const float4*)pt;        // sx, sy, w0, w1
        const float4 pt1 = *(const float4*)(pt + 4);  // w2, w3, sa, -
        const float wl[4] = { pt0.z, pt0.w, pt1.x, pt1.y };
        const float sx = pt0.x, sy = pt0.y;

        float acc[8] = {};

#pragma unroll
        for (int lvl = 0; lvl < 4; ++lvl) {
            const int   WW  = 256 >> lvl;
            const float inv = 0.25f / (float)(1 << lvl);
            const float w   = wl[lvl];

            const float ix = sx * inv - 0.5f;
            const float iy = sy * inv - 0.5f;
            const float x0f = floorf(ix), y0f = floorf(iy);
            const float wx1 = ix - x0f, wy1 = iy - y0f;
            const float wx0 = 1.f - wx1, wy0 = 1.f - wy1;
            const int x0 = (int)x0f, y0 = (int)y0f;
            const int x1 = x0 + 1,   y1 = y0 + 1;

            const float fx0 = (x0 >= 0 && x0 < WW) ? 1.f : 0.f;
            const float fx1 = (x1 >= 0 && x1 < WW) ? 1.f : 0.f;
            const float fy0 = (y0 >= 0 && y0 < WW) ? 1.f : 0.f;
            const float fy1 = (y1 >= 0 && y1 < WW) ? 1.f : 0.f;

            const int cx0 = min(max(x0, 0), WW - 1);
            const int cx1 = min(max(x1, 0), WW - 1);
            const int cy0 = min(max(y0, 0), WW - 1);
            const int cy1 = min(max(y1, 0), WW - 1);

            const __half* vb = (lvl == 0 ? lb0 : lvl == 1 ? lb1 : lvl == 2 ? lb2 : lb3) + choff;

            const uint4 v00 = *(const uint4*)(vb + ((size_t)cy0 * WW + cx0) * 256);
            const uint4 v01 = *(const uint4*)(vb + ((size_t)cy0 * WW + cx1) * 256);
            const uint4 v10 = *(const uint4*)(vb + ((size_t)cy1 * WW + cx0) * 256);
            const uint4 v11 = *(const uint4*)(vb + ((size_t)cy1 * WW + cx1) * 256);

            acc8(acc, v00, w * wx0 * wy0 * fx0 * fy0);
            acc8(acc, v01, w * wx1 * wy0 * fx1 * fy0);
            acc8(acc, v10, w * wx0 * wy1 * fx0 * fy1);
            acc8(acc, v11, w * wx1 * wy1 * fx1 * fy1);
        }

        const float sam = pt1.z;
        const float4 ca0 = *(const float4*)(CA + (size_t)q * EMB_ + choff);
        const float4 ca1 = *(const float4*)(CA + (size_t)q * EMB_ + choff + 4);

        __half2 h0 = __floats2half2_rn(acc[0] * ca0.x * sam, acc[1] * ca0.y * sam);
        __half2 h1 = __floats2half2_rn(acc[2] * ca0.z * sam, acc[3] * ca0.w * sam);
        __half2 h2 = __floats2half2_rn(acc[4] * ca1.x * sam, acc[5] * ca1.y * sam);
        __half2 h3 = __floats2half2_rn(acc[6] * ca1.z * sam, acc[7] * ca1.w * sam);
        uint4 o;
        o.x = *(uint32_t*)&h0; o.y = *(uint32_t*)&h1;
        o.z = *(uint32_t*)&h2; o.w = *(uint32_t*)&h3;
        *(uint4*)(X + (size_t)q * XDIM_ + p * CH_ + c8) = o;
    }
}

// ---------------- launch ----------------
static void* sym_addr(const void* symbol)
{
    void* p = nullptr;
    cudaGetSymbolAddress(&p, symbol);
    return p;
}

extern "C" void kernel_launch(void* const* d_in, const int* in_sizes, int n_in,
                              void* d_out, int out_size)
{
    const float* v0    = (const float*)d_in[0];
    const float* v1    = (const float*)d_in[1];
    const float* v2    = (const float*)d_in[2];
    const float* v3    = (const float*)d_in[3];
    const float* qc    = (const float*)d_in[4];
    const float* xyzrt = (const float*)d_in[5];
    // d_in[6] strides (int32) -- fixed [4,8,16,32], folded into constants
    const float* W_off = (const float*)d_in[7];
    const float* b_off = (const float*)d_in[8];
    const float* W_ca1 = (const float*)d_in[9];
    const float* W_ca2 = (const float*)d_in[10];
    const float* W_sa1 = (const float*)d_in[11];
    const float* W_sa2 = (const float*)d_in[12];
    const float* W_out = (const float*)d_in[13];
    const float* b_out = (const float*)d_in[14];
    float* out = (float*)d_out;

    __half* p_vt0 = (__half*)sym_addr(g_vt0);
    __half* p_vt1 = (__half*)sym_addr(g_vt1);
    __half* p_vt2 = (__half*)sym_addr(g_vt2);
    __half* p_vt3 = (__half*)sym_addr(g_vt3);
    float*  p_OFF = (float*)sym_addr(g_OFF);
    float*  p_HCA = (float*)sym_addr(g_HCA);
    float*  p_HSA = (float*)sym_addr(g_HSA);
    float*  p_CA  = (float*)sym_addr(g_CA);
    float*  p_SA  = (float*)sym_addr(g_SA);
    float*  p_PT  = (float*)sym_addr(g_PT);
    __half* p_Xh  = (__half*)sym_addr(g_Xh);
    __half* p_Wt  = (__half*)sym_addr(g_Wt);
    float*  p_PRT = (float*)sym_addr(g_PART);

    static bool init_done = false;
    static cudaStream_t s1 = 0, s2 = 0;
    static cudaEvent_t evR = 0, ev1 = 0, ev2 = 0;
    if (!init_done) {
        cudaFuncSetAttribute(gemm_mma, cudaFuncAttributeMaxDynamicSharedMemorySize, TC_SMEM);
        cudaStreamCreateWithFlags(&s1, cudaStreamNonBlocking);
        cudaStreamCreateWithFlags(&s2, cudaStreamNonBlocking);
        cudaEventCreateWithFlags(&evR, cudaEventDisableTiming);
        cudaEventCreateWithFlags(&ev1, cudaEventDisableTiming);
        cudaEventCreateWithFlags(&ev2, cudaEventDisableTiming);
        init_done = true;
    }

    // fork: side streams for the heavy transposes / weight conversion
    cudaEventRecord(evR, 0);
    cudaStreamWaitEvent(s1, evR, 0);
    cudaStreamWaitEvent(s2, evR, 0);

    // s1: level-0 transpose (the big one)
    transpose_cl<<<dim3(HW0_ / 32, B_), 256, 0, s1>>>(v0, p_vt0, HW0_);
    cudaEventRecord(ev1, s1);

    // s2: levels 1-3 + W_out convert
    transpose_cl<<<dim3(HW1_ / 32, B_), 256, 0, s2>>>(v1, p_vt1, HW1_);
    transpose_cl<<<dim3(HW2_ / 32, B_), 256, 0, s2>>>(v2, p_vt2, HW2_);
    transpose_cl<<<dim3(HW3_ / 32, B_), 256, 0, s2>>>(v3, p_vt3, HW3_);
    wt_convert<<<dim3(XDIM_ / 32, EMB_ / 32), dim3(32, 8), 0, s2>>>(W_out, p_Wt);
    cudaEventRecord(ev2, s2);

    // capture stream: projections + point prep (independent of transposes)
    const int gm = (NQ_ + 63) / 64;  // 32
    gemm_small<<<dim3(gm, 384 / 64), 256>>>(qc, W_off, b_off, p_OFF, NQ_, 384, EMB_, 0);
    gemm_small<<<dim3(gm, 1),        256>>>(qc, W_ca1, nullptr, p_HCA, NQ_, 64,  EMB_, 1);
    gemm_small<<<dim3(gm, 256 / 64), 256>>>(p_HCA, W_ca2, nullptr, p_CA, NQ_, 256, 64, 2);
    gemm_small<<<dim3(gm, 1),        256>>>(qc, W_sa1, nullptr, p_HSA, NQ_, 64,  EMB_, 1);
    gemm_small<<<dim3(gm, 128 / 64), 256>>>(p_HSA, W_sa2, nullptr, p_SA, NQ_, 128, 64, 2);
    point_prep<<<NQ_, P_>>>(p_OFF, xyzrt, p_SA, p_PT);

    // join
    cudaStreamWaitEvent(0, ev1, 0);
    cudaStreamWaitEvent(0, ev2, 0);

    // sampler -> X fp16
    sampler_kernel<<<NQ_, 256>>>(p_PT, p_CA, p_Xh);

    // final GEMM on HMMA tensor path + reduce
    gemm_mma<<<dim3(MPAD_ / 128, EMB_ / 128, SK_), 256, TC_SMEM>>>(p_Xh, p_Wt, p_PRT);
    reduce_out<<<(NQ_ * EMB_ + 255) / 256, 256>>>(p_PRT, b_out, qc, out, NQ_ * EMB_);
}